// round 4
// baseline (speedup 1.0000x reference)
#include <cuda_runtime.h>
#include <math.h>

#define NQ 12
#define TPB 256
#define NB 256

typedef unsigned long long u64;

__device__ __forceinline__ u64 pk(float lo, float hi) {
    u64 r;
    asm("mov.b64 %0,{%1,%2};" : "=l"(r)
        : "r"(__float_as_uint(lo)), "r"(__float_as_uint(hi)));
    return r;
}
__device__ __forceinline__ void upk(u64 v, float& lo, float& hi) {
    unsigned a, b;
    asm("mov.b64 {%0,%1},%2;" : "=r"(a), "=r"(b) : "l"(v));
    lo = __uint_as_float(a); hi = __uint_as_float(b);
}
__device__ __forceinline__ u64 sp(float f) { return pk(f, f); }
__device__ __forceinline__ u64 f2(u64 a, u64 b, u64 c) {
    u64 d;
    asm("fma.rn.f32x2 %0,%1,%2,%3;" : "=l"(d) : "l"(a), "l"(b), "l"(c));
    return d;
}
__device__ __forceinline__ u64 m2(u64 a, u64 b) {
    u64 d;
    asm("mul.rn.f32x2 %0,%1,%2;" : "=l"(d) : "l"(a), "l"(b));
    return d;
}
__device__ __forceinline__ u64 swp(u64 v) {
    float l, h; upk(v, l, h); return pk(h, l);
}

__device__ __forceinline__ float2 cmulc(float2 x, float2 y) {
    return make_float2(x.x * y.x - x.y * y.y, x.x * y.y + x.y * y.x);
}

__device__ __forceinline__ float gelu_f(float x) {
    return 0.5f * x * (1.0f + erff(x * 0.7071067811865476f));
}

// Composed CNOT-ring permutation (CNOT(0,1)..CNOT(10,11),CNOT(11,0)).
// Qubit w lives at bit position (11-w). Linear over GF(2).
__device__ __forceinline__ int permdst(int idx) {
    int y = idx;
    y ^= y >> 1; y ^= y >> 2; y ^= y >> 4; y ^= y >> 8;
    return (y & 0x7FF) | (((y ^ (idx >> 11)) & 1) << 11);
}

// vectorized 2x2 complex gate on a packed pair (each u64 = 2 independent amps)
__device__ __forceinline__ void vgate(u64& X0, u64& Y0, u64& X1, u64& Y1,
    u64 g0x, u64 g0y, u64 g0yn, u64 g1x, u64 g1y, u64 g1yn,
    u64 g2x, u64 g2y, u64 g2yn, u64 g3x, u64 g3y, u64 g3yn)
{
    u64 nX0 = f2(g1yn, Y1, f2(g1x, X1, f2(g0yn, Y0, m2(g0x, X0))));
    u64 nY0 = f2(g1y,  X1, f2(g1x, Y1, f2(g0y,  X0, m2(g0x, Y0))));
    u64 nX1 = f2(g3yn, Y1, f2(g3x, X1, f2(g2yn, Y0, m2(g2x, X0))));
    u64 nY1 = f2(g3y,  X1, f2(g3x, Y1, f2(g2y,  X0, m2(g2x, Y0))));
    X0 = nX0; Y0 = nY0; X1 = nX1; Y1 = nY1;
}

// one phase: 3 k-bit gates (qubits Q0, Q0-1, Q0-2 on reg bits 0,1,2)
// + pack gate (qubit Q0-3). G = per-layer gate-splat table Gk[l][q][12].
__device__ __forceinline__ void phase_gates(u64* SX, u64* SY,
                                            const u64 (*G)[12], int Q0)
{
    #pragma unroll
    for (int rb = 0; rb < 3; rb++) {
        const u64* g = G[Q0 - rb];
        u64 g0x = g[0], g0y = g[1], g0yn = g[2];
        u64 g1x = g[3], g1y = g[4], g1yn = g[5];
        u64 g2x = g[6], g2y = g[7], g2yn = g[8];
        u64 g3x = g[9], g3y = g[10], g3yn = g[11];
        #pragma unroll
        for (int k = 0; k < 8; k++) {
            if (!((k >> rb) & 1)) {
                const int k1 = k | (1 << rb);
                vgate(SX[k], SY[k], SX[k1], SY[k1],
                      g0x, g0y, g0yn, g1x, g1y, g1yn,
                      g2x, g2y, g2yn, g3x, g3y, g3yn);
            }
        }
    }
    // pack gate (qubit Q0-3) : new_lo = G0*lo + G1*hi ; new_hi = G2*lo + G3*hi
    const u64* p = G[Q0 - 3];
    u64 Dx = p[0], Dy = p[1], Dyn = p[2];
    u64 Ox = p[3], Oy = p[4], Oyn = p[5];
    #pragma unroll
    for (int k = 0; k < 8; k++) {
        u64 sX = swp(SX[k]), sY = swp(SY[k]);
        u64 nX = f2(Oyn, sY, f2(Ox, sX, f2(Dyn, SY[k], m2(Dx, SX[k]))));
        u64 nY = f2(Oy,  sX, f2(Ox, sY, f2(Dy,  SX[k], m2(Dx, SY[k]))));
        SX[k] = nX; SY[k] = nY;
    }
}

// RT C: perm scatter (phase-3 regs, pack=b3) + gather into phase-1 (pack=b11).
// smem map F_C(d) = ((d ^ (d>>5)) & 0xF) | (d & 0xFF0)   (conflict-free both sides)
__device__ __forceinline__ void rt_perm(u64* SX, u64* SY, float2* fb,
                                        int tid, unsigned czsel)
{
    #pragma unroll
    for (int k = 0; k < 8; k++) {
        int src = k | (tid << 4);
        int d0 = permdst(src);
        int d1 = d0 ^ 0x80F;           // flip src bit3 -> flips d0..d3, d11
        int s0 = ((d0 ^ (d0 >> 5)) & 0xF) | (d0 & 0xFF0);
        int s1 = s0 ^ 0x80F;
        float xl, xh, yl, yh;
        upk(SX[k], xl, xh); upk(SY[k], yl, yh);
        unsigned g0 = ((unsigned)__popc((d0 & (d0 >> 2)) & 0x2AA) & czsel) << 31;
        unsigned g1 = ((unsigned)__popc((d1 & (d1 >> 2)) & 0x2AA) & czsel) << 31;
        xl = __uint_as_float(__float_as_uint(xl) ^ g0);
        yl = __uint_as_float(__float_as_uint(yl) ^ g0);
        xh = __uint_as_float(__float_as_uint(xh) ^ g1);
        yh = __uint_as_float(__float_as_uint(yh) ^ g1);
        fb[s0] = make_float2(xl, yl);
        fb[s1] = make_float2(xh, yh);
    }
    __syncthreads();
    #pragma unroll
    for (int k = 0; k < 8; k++) {
        // gather phase-1: idx = tid | (k<<8) | (p11<<11)
        int nib = ((tid ^ (tid >> 5)) & 0xF) ^ ((k & 1) << 3);
        int s0 = nib | (tid & 0xF0) | (k << 8);
        float2 lo = fb[s0];
        float2 hi = fb[s0 | 0x800];
        SX[k] = pk(lo.x, hi.x);
        SY[k] = pk(lo.y, hi.y);
    }
}

__global__ void __launch_bounds__(TPB, 2)
qpu_kernel(const float* __restrict__ x,
           const float* __restrict__ W1, const float* __restrict__ b1,
           const float* __restrict__ g_ln, const float* __restrict__ b_ln,
           const float* __restrict__ W2, const float* __restrict__ b2,
           const float* __restrict__ W3, const float* __restrict__ b3,
           const float* __restrict__ qw,
           const float* __restrict__ W4, const float* __restrict__ b4,
           const float* __restrict__ W5, const float* __restrict__ b5,
           float* __restrict__ out)
{
    // dynamic: 2 ping-pong float2 buffers, 4096 each = 64 KB
    extern __shared__ float2 fsm[];
    __shared__ __align__(16) float xrow[256];
    __shared__ __align__(16) float h1s[128];
    __shared__ __align__(16) float hns[128];
    __shared__ __align__(16) float h2s[64];
    __shared__ u64 Gk[5][NQ][12];         // pre-splatted gate coeffs, layers 1..5
    __shared__ float2 v0s[NQ], v1s[NQ];   // initial per-qubit product-state vectors
    __shared__ float cqs[NQ], sqs[NQ];    // re-upload RY half-angle cos/sin
    __shared__ float red0[8], red1[8];
    __shared__ float stats[2];
    __shared__ float wz[8][3];
    __shared__ float qv[3];
    __shared__ float h4s[32];

    const int tid = threadIdx.x;
    const int bidx = blockIdx.x;
    const int lane = tid & 31, wid = tid >> 5;

    xrow[tid] = x[bidx * 256 + tid];
    __syncthreads();

    // ---- h1 = gelu(x @ W1^T + b1), 128 outputs ----
    if (tid < 128) {
        const float4* wr = (const float4*)(W1 + tid * 256);
        const float4* xr = (const float4*)xrow;
        float acc0 = 0.f, acc1 = 0.f;
        #pragma unroll 8
        for (int k = 0; k < 64; k += 2) {
            float4 w = wr[k], xv = xr[k];
            acc0 = fmaf(w.x, xv.x, acc0); acc0 = fmaf(w.y, xv.y, acc0);
            acc0 = fmaf(w.z, xv.z, acc0); acc0 = fmaf(w.w, xv.w, acc0);
            float4 w2_ = wr[k + 1], xv2 = xr[k + 1];
            acc1 = fmaf(w2_.x, xv2.x, acc1); acc1 = fmaf(w2_.y, xv2.y, acc1);
            acc1 = fmaf(w2_.z, xv2.z, acc1); acc1 = fmaf(w2_.w, xv2.w, acc1);
        }
        h1s[tid] = gelu_f(acc0 + acc1 + b1[tid]);
    }
    __syncthreads();

    // ---- layernorm over 128 ----
    {
        float v = (tid < 128) ? h1s[tid] : 0.f;
        float s = v, ss = v * v;
        #pragma unroll
        for (int o = 16; o; o >>= 1) {
            s += __shfl_xor_sync(~0u, s, o);
            ss += __shfl_xor_sync(~0u, ss, o);
        }
        if (lane == 0) { red0[wid] = s; red1[wid] = ss; }
    }
    __syncthreads();
    if (tid == 0) {
        float s = 0.f, ss = 0.f;
        #pragma unroll
        for (int w = 0; w < 8; w++) { s += red0[w]; ss += red1[w]; }
        float mu = s * (1.f / 128.f);
        float var = ss * (1.f / 128.f) - mu * mu;
        stats[0] = mu; stats[1] = rsqrtf(var + 1e-5f);
    }
    __syncthreads();
    if (tid < 128)
        hns[tid] = (h1s[tid] - stats[0]) * stats[1] * g_ln[tid] + b_ln[tid];
    __syncthreads();

    // ---- h2 = gelu(hn @ W2^T + b2), 64 outputs ----
    if (tid < 64) {
        const float4* wr = (const float4*)(W2 + tid * 128);
        const float4* hr = (const float4*)hns;
        float acc = 0.f;
        #pragma unroll 8
        for (int k = 0; k < 32; k++) {
            float4 w = wr[k], h = hr[k];
            acc = fmaf(w.x, h.x, acc); acc = fmaf(w.y, h.y, acc);
            acc = fmaf(w.z, h.z, acc); acc = fmaf(w.w, h.w, acc);
        }
        h2s[tid] = gelu_f(acc + b2[tid]);
    }
    __syncthreads();

    // ---- xq = tanh(h2 @ W3^T + b3); enc = xq*pi^2; init vectors + re-upload cs ----
    if (tid < NQ) {
        const float* wr = W3 + tid * 64;
        float acc = 0.f;
        #pragma unroll
        for (int k = 0; k < 64; k++) acc = fmaf(wr[k], h2s[k], acc);
        float xqv = tanhf(acc + b3[tid]);
        float e = xqv * 9.869604401089358f;   // pi^2
        float se, ce; sincosf(0.5f * e, &se, &ce);
        const float* wp = qw + tid * 3;
        float w0 = wp[0], w1 = wp[1], w2v = wp[2];
        float sh, ch; sincosf(0.5f * w1, &sh, &ch);
        float sa, ca; sincosf(0.5f * (w0 + w2v), &sa, &ca);
        float sb, cb; sincosf(0.5f * (w0 - w2v), &sb, &cb);
        float2 u00 = make_float2(ch * ca, -ch * sa);
        float2 u01 = make_float2(-sh * cb, -sh * sb);
        float2 u10 = make_float2(sh * cb, -sh * sb);
        float2 u11 = make_float2(ch * ca, ch * sa);
        v0s[tid] = make_float2(u00.x * ce + u01.x * se, u00.y * ce + u01.y * se);
        v1s[tid] = make_float2(u10.x * ce + u11.x * se, u10.y * ce + u11.y * se);
        float s4, c4; sincosf(0.25f * e, &s4, &c4);
        cqs[tid] = c4; sqs[tid] = s4;
    }
    __syncthreads();

    // ---- pre-splatted merged gate tables for layers 1..5 ----
    if (tid < 60) {
        int L = tid / 12 + 1, q = tid - (L - 1) * 12;
        const float* wp = qw + (L * NQ + q) * 3;
        float w0 = wp[0], w1 = wp[1], w2v = wp[2];
        float sh, ch; sincosf(0.5f * w1, &sh, &ch);
        float sa, ca; sincosf(0.5f * (w0 + w2v), &sa, &ca);
        float sb, cb; sincosf(0.5f * (w0 - w2v), &sb, &cb);
        float2 U0 = make_float2(ch * ca, -ch * sa);
        float2 U1 = make_float2(-sh * cb, -sh * sb);
        float2 U2 = make_float2(sh * cb, -sh * sb);
        float2 U3 = make_float2(ch * ca, ch * sa);
        if (L & 1) {   // fold RY(enc/2) re-upload (emitted after even layers)
            float cf = cqs[q], sf = sqs[q];
            float2 n0 = make_float2(U0.x * cf + U1.x * sf, U0.y * cf + U1.y * sf);
            float2 n1 = make_float2(-U0.x * sf + U1.x * cf, -U0.y * sf + U1.y * cf);
            float2 n2 = make_float2(U2.x * cf + U3.x * sf, U2.y * cf + U3.y * sf);
            float2 n3 = make_float2(-U2.x * sf + U3.x * cf, -U2.y * sf + U3.y * cf);
            U0 = n0; U1 = n1; U2 = n2; U3 = n3;
        }
        u64* g = Gk[L - 1][q];
        if ((q & 3) == 0) {   // pack-gate form (qubits 0,4,8)
            g[0] = pk(U0.x, U3.x); g[1] = pk(U0.y, U3.y); g[2] = pk(-U0.y, -U3.y);
            g[3] = pk(U1.x, U2.x); g[4] = pk(U1.y, U2.y); g[5] = pk(-U1.y, -U2.y);
        } else {              // k-gate splat form
            g[0] = sp(U0.x); g[1]  = sp(U0.y); g[2]  = sp(-U0.y);
            g[3] = sp(U1.x); g[4]  = sp(U1.y); g[5]  = sp(-U1.y);
            g[6] = sp(U2.x); g[7]  = sp(U2.y); g[8]  = sp(-U2.y);
            g[9] = sp(U3.x); g[10] = sp(U3.y); g[11] = sp(-U3.y);
        }
    }
    __syncthreads();

    // ---- init product state directly in PHASE-3 layout ----
    // phase-3 idx = k(b0..2) | pack(b3) | tid(b4..11); bit p -> qubit 11-p
    u64 SX[8], SY[8];
    {
        float2 cm = (tid & 1) ? v1s[7] : v0s[7];     // p=4, qubit 7
        #pragma unroll
        for (int p = 5; p < 12; p++) {
            float2 f = ((tid >> (p - 4)) & 1) ? v1s[11 - p] : v0s[11 - p];
            cm = cmulc(cm, f);
        }
        float2 p8a = v0s[8], p8b = v1s[8];
        #pragma unroll
        for (int k = 0; k < 8; k++) {
            float2 a = cm;
            #pragma unroll
            for (int j = 0; j < 3; j++) {
                float2 f = ((k >> j) & 1) ? v1s[11 - j] : v0s[11 - j];
                a = cmulc(a, f);
            }
            float2 lo = cmulc(a, p8a);
            float2 hi = cmulc(a, p8b);
            SX[k] = pk(lo.x, hi.x);
            SY[k] = pk(lo.y, hi.y);
        }
    }

    int b = 0;
    // layer-0 gates are folded into init; apply layer-0 perm (no CZ)
    rt_perm(SX, SY, fsm + b * 4096, tid, 0u);
    b ^= 1;

    // ---- layers 1..5 ----
    for (int l = 1; l < 6; l++) {
        const u64 (*G)[12] = Gk[l - 1];

        // PHASE 1: qubits 3,2,1 (reg bits = idx b8..b10) + pack qubit 0 (b11)
        phase_gates(SX, SY, G, 3);

        // RT A: phase-1 -> phase-2 (F_A = identity on canonical idx)
        {
            float2* fb = fsm + b * 4096;
            #pragma unroll
            for (int k = 0; k < 8; k++) {
                int i0 = (k << 8) | tid;
                float xl, xh, yl, yh;
                upk(SX[k], xl, xh); upk(SY[k], yl, yh);
                fb[i0] = make_float2(xl, yl);
                fb[i0 | 0x800] = make_float2(xh, yh);
            }
            __syncthreads();
            int base = (tid & 0xF) | (((tid >> 4) & 1) << 8) | ((tid >> 5) << 9);
            #pragma unroll
            for (int k = 0; k < 8; k++) {
                float2 lo = fb[base | (k << 4)];
                float2 hi = fb[base | (k << 4) | 0x80];
                SX[k] = pk(lo.x, hi.x);
                SY[k] = pk(lo.y, hi.y);
            }
            b ^= 1;
        }

        // PHASE 2: qubits 7,6,5 (reg bits = idx b4..b6) + pack qubit 4 (b7)
        phase_gates(SX, SY, G, 7);

        // RT B: phase-2 -> phase-3 ; F_B(idx) = ((idx^(idx>>4))&0xF) | (idx&0xFF0)
        {
            float2* fb = fsm + b * 4096;
            int sb = (((tid >> 4) & 1) << 8) | ((tid >> 5) << 9);
            #pragma unroll
            for (int k = 0; k < 8; k++) {
                int s0 = (((tid & 0xF) ^ k)) | (k << 4) | sb;
                float xl, xh, yl, yh;
                upk(SX[k], xl, xh); upk(SY[k], yl, yh);
                fb[s0] = make_float2(xl, yl);
                fb[s0 ^ 0x88] = make_float2(xh, yh);
            }
            __syncthreads();
            #pragma unroll
            for (int k = 0; k < 8; k++) {
                int s0 = (k ^ (tid & 0xF)) | (tid << 4);
                float2 lo = fb[s0];
                float2 hi = fb[s0 ^ 8];
                SX[k] = pk(lo.x, hi.x);
                SY[k] = pk(lo.y, hi.y);
            }
            b ^= 1;
        }

        // PHASE 3: qubits 11,10,9 (reg bits = idx b0..b2) + pack qubit 8 (b3)
        phase_gates(SX, SY, G, 11);

        // RT C: CNOT-ring perm (+CZ on odd layers) -> phase-1 of next layer
        if (l < 5) {
            rt_perm(SX, SY, fsm + b * 4096, tid, (unsigned)(l & 1));
            b ^= 1;
        }
    }

    // ---- measurement from phase-3 layout; layer-5 perm folded into signs ----
    // pack partner (b3 flip) flips d11 (and d0..d3) but not d10/d9.
    float z0 = 0.f, z1 = 0.f, z2 = 0.f;
    #pragma unroll
    for (int k = 0; k < 8; k++) {
        int src = k | (tid << 4);
        int d0 = permdst(src);
        u64 P = f2(SY[k], SY[k], m2(SX[k], SX[k]));
        float pl, ph; upk(P, pl, ph);
        float sum = pl + ph, dif = pl - ph;
        z0 += ((d0 >> 11) & 1) ? -dif : dif;
        z1 += ((d0 >> 10) & 1) ? -sum : sum;
        z2 += ((d0 >> 9) & 1) ? -sum : sum;
    }
    #pragma unroll
    for (int o = 16; o; o >>= 1) {
        z0 += __shfl_xor_sync(~0u, z0, o);
        z1 += __shfl_xor_sync(~0u, z1, o);
        z2 += __shfl_xor_sync(~0u, z2, o);
    }
    if (lane == 0) { wz[wid][0] = z0; wz[wid][1] = z1; wz[wid][2] = z2; }
    __syncthreads();
    if (tid < 3) {
        float t = 0.f;
        #pragma unroll
        for (int w = 0; w < 8; w++) t += wz[w][tid];
        qv[tid] = t;
    }
    __syncthreads();

    // ---- head: gelu(q @ W4^T + b4) @ W5^T + b5 ----
    if (tid < 32) {
        float acc = b4[tid];
        acc = fmaf(W4[tid * 3 + 0], qv[0], acc);
        acc = fmaf(W4[tid * 3 + 1], qv[1], acc);
        acc = fmaf(W4[tid * 3 + 2], qv[2], acc);
        h4s[tid] = gelu_f(acc);
    }
    __syncthreads();
    if (tid < 64) {
        const float* wr = W5 + tid * 32;
        float acc = b5[tid];
        #pragma unroll
        for (int j = 0; j < 32; j++) acc = fmaf(wr[j], h4s[j], acc);
        out[bidx * 64 + tid] = acc;
    }
}

extern "C" void kernel_launch(void* const* d_in, const int* in_sizes, int n_in,
                              void* d_out, int out_size)
{
    const float* x    = (const float*)d_in[0];
    const float* W1   = (const float*)d_in[1];
    const float* b1   = (const float*)d_in[2];
    const float* g_ln = (const float*)d_in[3];
    const float* b_ln = (const float*)d_in[4];
    const float* W2   = (const float*)d_in[5];
    const float* b2   = (const float*)d_in[6];
    const float* W3   = (const float*)d_in[7];
    const float* b3   = (const float*)d_in[8];
    const float* qw   = (const float*)d_in[9];
    const float* W4   = (const float*)d_in[10];
    const float* b4   = (const float*)d_in[11];
    const float* W5   = (const float*)d_in[12];
    const float* b5   = (const float*)d_in[13];

    const size_t shmem = 8192 * sizeof(float2);  // 64 KB: 2 ping-pong float2 buffers
    cudaFuncSetAttribute(qpu_kernel, cudaFuncAttributeMaxDynamicSharedMemorySize,
                         (int)shmem);
    qpu_kernel<<<NB, TPB, shmem>>>(x, W1, b1, g_ln, b_ln, W2, b2, W3, b3, qw,
                                   W4, b4, W5, b5, (float*)d_out);
}

// round 5
// speedup vs baseline: 1.1293x; 1.1293x over previous
#include <cuda_runtime.h>
#include <math.h>

#define NQ 12
#define TPB 256
#define NB 256

typedef unsigned long long u64;

__device__ __forceinline__ u64 pk(float lo, float hi) {
    u64 r;
    asm("mov.b64 %0,{%1,%2};" : "=l"(r)
        : "r"(__float_as_uint(lo)), "r"(__float_as_uint(hi)));
    return r;
}
__device__ __forceinline__ void upk(u64 v, float& lo, float& hi) {
    unsigned a, b;
    asm("mov.b64 {%0,%1},%2;" : "=r"(a), "=r"(b) : "l"(v));
    lo = __uint_as_float(a); hi = __uint_as_float(b);
}
__device__ __forceinline__ u64 sp(float f) { return pk(f, f); }
__device__ __forceinline__ u64 f2(u64 a, u64 b, u64 c) {
    u64 d;
    asm("fma.rn.f32x2 %0,%1,%2,%3;" : "=l"(d) : "l"(a), "l"(b), "l"(c));
    return d;
}
__device__ __forceinline__ u64 m2(u64 a, u64 b) {
    u64 d;
    asm("mul.rn.f32x2 %0,%1,%2;" : "=l"(d) : "l"(a), "l"(b));
    return d;
}
__device__ __forceinline__ u64 swp(u64 v) {
    float l, h; upk(v, l, h); return pk(h, l);
}

__device__ __forceinline__ float2 cmulc(float2 x, float2 y) {
    return make_float2(x.x * y.x - x.y * y.y, x.x * y.y + x.y * y.x);
}

__device__ __forceinline__ float gelu_f(float x) {
    return 0.5f * x * (1.0f + erff(x * 0.7071067811865476f));
}

// Composed CNOT-ring permutation (CNOT(0,1)..CNOT(10,11),CNOT(11,0)).
// Qubit w lives at bit position (11-w). LINEAR over GF(2):
// permdst(a^b) == permdst(a)^permdst(b).
__device__ __forceinline__ int permdst(int idx) {
    int y = idx;
    y ^= y >> 1; y ^= y >> 2; y ^= y >> 4; y ^= y >> 8;
    return (y & 0x7FF) | (((y ^ (idx >> 11)) & 1) << 11);
}

// ---- symmetric-form gates: matrix stored as float4 (U0.x,U0.y,U1.x,U1.y),
//      with U11 = conj(U00), U10 = (-U01.x, U01.y). Survives the RY fold. ----

// k-bit gate on register pair (4 amps per call via u64 packing)
__device__ __forceinline__ void kgate(u64* SX, u64* SY, float4 m, int rb)
{
    u64 g0x = sp(m.x),  g0y = sp(m.y), g0yn = sp(-m.y);
    u64 g1x = sp(m.z),  g1xn = sp(-m.z);
    u64 g1y = sp(m.w),  g1yn = sp(-m.w);
    #pragma unroll
    for (int k = 0; k < 8; k++) {
        if (!((k >> rb) & 1)) {
            const int k1 = k | (1 << rb);
            u64 X0 = SX[k], Y0 = SY[k], X1 = SX[k1], Y1 = SY[k1];
            SX[k]  = f2(g1yn, Y1, f2(g1x, X1, f2(g0yn, Y0, m2(g0x, X0))));
            SY[k]  = f2(g1y,  X1, f2(g1x, Y1, f2(g0y,  X0, m2(g0x, Y0))));
            SX[k1] = f2(g0y,  Y1, f2(g0x, X1, f2(g1yn, Y0, m2(g1xn, X0))));
            SY[k1] = f2(g0yn, X1, f2(g0x, Y1, f2(g1y,  X0, m2(g1xn, Y0))));
        }
    }
}

// pack-lane gate (qubit living on the u64 lo/hi halves)
__device__ __forceinline__ void pgate(u64* SX, u64* SY, float4 m)
{
    u64 Dx  = sp(m.x);
    u64 Dy  = pk(m.y, -m.y), Dyn = pk(-m.y, m.y);
    u64 Ox  = pk(m.z, -m.z);
    u64 Oy  = sp(m.w), Oyn = sp(-m.w);
    #pragma unroll
    for (int k = 0; k < 8; k++) {
        u64 sX = swp(SX[k]), sY = swp(SY[k]);
        u64 nX = f2(Oyn, sY, f2(Ox, sX, f2(Dyn, SY[k], m2(Dx, SX[k]))));
        u64 nY = f2(Oy,  sX, f2(Ox, sY, f2(Dy,  SX[k], m2(Dx, SY[k]))));
        SX[k] = nX; SY[k] = nY;
    }
}

// lane-bit gate via warp shuffle
__device__ __forceinline__ void sgate(u64* SX, u64* SY, float4 m, int p, int lane)
{
    const int sb = (lane >> p) & 1;
    float dY = sb ? -m.y : m.y;
    float oX = sb ? -m.z : m.z;
    u64 gdx = sp(m.x), gdy = sp(dY), gdyn = sp(-dY);
    u64 gox = sp(oX),  goy = sp(m.w), goyn = sp(-m.w);
    #pragma unroll
    for (int k = 0; k < 8; k++) {
        float xl, xh, yl, yh;
        upk(SX[k], xl, xh); upk(SY[k], yl, yh);
        float oxl = __shfl_xor_sync(~0u, xl, 1 << p);
        float oxh = __shfl_xor_sync(~0u, xh, 1 << p);
        float oyl = __shfl_xor_sync(~0u, yl, 1 << p);
        float oyh = __shfl_xor_sync(~0u, yh, 1 << p);
        u64 OX = pk(oxl, oxh), OY = pk(oyl, oyh);
        u64 nX = f2(goyn, OY, f2(gox, OX, f2(gdyn, SY[k], m2(gdx, SX[k]))));
        u64 nY = f2(goy,  OX, f2(gox, OY, f2(gdy,  SX[k], m2(gdx, SY[k]))));
        SX[k] = nX; SY[k] = nY;
    }
}

__global__ void __launch_bounds__(TPB, 2)
qpu_kernel(const float* __restrict__ x,
           const float* __restrict__ W1, const float* __restrict__ b1,
           const float* __restrict__ g_ln, const float* __restrict__ b_ln,
           const float* __restrict__ W2, const float* __restrict__ b2,
           const float* __restrict__ W3, const float* __restrict__ b3,
           const float* __restrict__ qw,
           const float* __restrict__ W4, const float* __restrict__ b4,
           const float* __restrict__ W5, const float* __restrict__ b5,
           float* __restrict__ out)
{
    // dynamic: 2 ping-pong float2 buffers, 4096 each = 64 KB
    extern __shared__ float2 fsm[];
    __shared__ __align__(16) float xrow[256];
    __shared__ __align__(16) float h1s[128];
    __shared__ __align__(16) float hns[128];
    __shared__ __align__(16) float h2s[64];
    __shared__ float4 Mm[5][NQ];          // merged gates (U0.x,U0.y,U1.x,U1.y)
    __shared__ float2 v0s[NQ], v1s[NQ];   // initial per-qubit product-state vectors
    __shared__ float cqs[NQ], sqs[NQ];    // re-upload RY half-angle cos/sin
    __shared__ float red0[8], red1[8];
    __shared__ float stats[2];
    __shared__ float wz[8][3];
    __shared__ float qv[3];
    __shared__ float h4s[32];

    const int tid = threadIdx.x;
    const int bidx = blockIdx.x;
    const int lane = tid & 31, wid = tid >> 5;

    xrow[tid] = x[bidx * 256 + tid];
    __syncthreads();

    // ---- h1 = gelu(x @ W1^T + b1), 128 outputs ----
    if (tid < 128) {
        const float4* wr = (const float4*)(W1 + tid * 256);
        const float4* xr = (const float4*)xrow;
        float acc0 = 0.f, acc1 = 0.f;
        #pragma unroll 8
        for (int k = 0; k < 64; k += 2) {
            float4 w = wr[k], xv = xr[k];
            acc0 = fmaf(w.x, xv.x, acc0); acc0 = fmaf(w.y, xv.y, acc0);
            acc0 = fmaf(w.z, xv.z, acc0); acc0 = fmaf(w.w, xv.w, acc0);
            float4 w2_ = wr[k + 1], xv2 = xr[k + 1];
            acc1 = fmaf(w2_.x, xv2.x, acc1); acc1 = fmaf(w2_.y, xv2.y, acc1);
            acc1 = fmaf(w2_.z, xv2.z, acc1); acc1 = fmaf(w2_.w, xv2.w, acc1);
        }
        h1s[tid] = gelu_f(acc0 + acc1 + b1[tid]);
    }
    __syncthreads();

    // ---- layernorm over 128 ----
    {
        float v = (tid < 128) ? h1s[tid] : 0.f;
        float s = v, ss = v * v;
        #pragma unroll
        for (int o = 16; o; o >>= 1) {
            s += __shfl_xor_sync(~0u, s, o);
            ss += __shfl_xor_sync(~0u, ss, o);
        }
        if (lane == 0) { red0[wid] = s; red1[wid] = ss; }
    }
    __syncthreads();
    if (tid == 0) {
        float s = 0.f, ss = 0.f;
        #pragma unroll
        for (int w = 0; w < 8; w++) { s += red0[w]; ss += red1[w]; }
        float mu = s * (1.f / 128.f);
        float var = ss * (1.f / 128.f) - mu * mu;
        stats[0] = mu; stats[1] = rsqrtf(var + 1e-5f);
    }
    __syncthreads();
    if (tid < 128)
        hns[tid] = (h1s[tid] - stats[0]) * stats[1] * g_ln[tid] + b_ln[tid];
    __syncthreads();

    // ---- h2 = gelu(hn @ W2^T + b2), 64 outputs ----
    if (tid < 64) {
        const float4* wr = (const float4*)(W2 + tid * 128);
        const float4* hr = (const float4*)hns;
        float acc = 0.f;
        #pragma unroll 8
        for (int k = 0; k < 32; k++) {
            float4 w = wr[k], h = hr[k];
            acc = fmaf(w.x, h.x, acc); acc = fmaf(w.y, h.y, acc);
            acc = fmaf(w.z, h.z, acc); acc = fmaf(w.w, h.w, acc);
        }
        h2s[tid] = gelu_f(acc + b2[tid]);
    }
    __syncthreads();

    // ---- xq = tanh(h2 @ W3^T + b3); enc = xq*pi^2; init vectors + re-upload cs ----
    if (tid < NQ) {
        const float* wr = W3 + tid * 64;
        float acc = 0.f;
        #pragma unroll
        for (int k = 0; k < 64; k++) acc = fmaf(wr[k], h2s[k], acc);
        float xqv = tanhf(acc + b3[tid]);
        float e = xqv * 9.869604401089358f;   // pi^2
        float se, ce; sincosf(0.5f * e, &se, &ce);
        const float* wp = qw + tid * 3;
        float w0 = wp[0], w1 = wp[1], w2v = wp[2];
        float sh, ch; sincosf(0.5f * w1, &sh, &ch);
        float sa, ca; sincosf(0.5f * (w0 + w2v), &sa, &ca);
        float sb, cb; sincosf(0.5f * (w0 - w2v), &sb, &cb);
        float2 u00 = make_float2(ch * ca, -ch * sa);
        float2 u01 = make_float2(-sh * cb, -sh * sb);
        float2 u10 = make_float2(sh * cb, -sh * sb);
        float2 u11 = make_float2(ch * ca, ch * sa);
        v0s[tid] = make_float2(u00.x * ce + u01.x * se, u00.y * ce + u01.y * se);
        v1s[tid] = make_float2(u10.x * ce + u11.x * se, u10.y * ce + u11.y * se);
        float s4, c4; sincosf(0.25f * e, &s4, &c4);
        cqs[tid] = c4; sqs[tid] = s4;
    }
    __syncthreads();

    // ---- merged gate matrices for layers 1..5 (symmetric form: U0,U1 only) ----
    if (tid < 60) {
        int L = tid / 12 + 1, q = tid - (L - 1) * 12;
        const float* wp = qw + (L * NQ + q) * 3;
        float w0 = wp[0], w1 = wp[1], w2v = wp[2];
        float sh, ch; sincosf(0.5f * w1, &sh, &ch);
        float sa, ca; sincosf(0.5f * (w0 + w2v), &sa, &ca);
        float sb, cb; sincosf(0.5f * (w0 - w2v), &sb, &cb);
        float2 U0 = make_float2(ch * ca, -ch * sa);
        float2 U1 = make_float2(-sh * cb, -sh * sb);
        if (L & 1) {   // fold RY(enc/2) re-upload (emitted after even layers)
            float cf = cqs[q], sf = sqs[q];
            float2 n0 = make_float2(U0.x * cf + U1.x * sf, U0.y * cf + U1.y * sf);
            float2 n1 = make_float2(-U0.x * sf + U1.x * cf, -U0.y * sf + U1.y * cf);
            U0 = n0; U1 = n1;
        }
        Mm[L - 1][q] = make_float4(U0.x, U0.y, U1.x, U1.y);
    }
    __syncthreads();

    // ============ statevector ============
    // Canonical C: SX[k]/SY[k] hold idx (k<<8)|tid (lo) and |0x800 (hi).
    //   k bits = idx 8..10 (qubits 3,2,1), pack = idx 11 (qubit 0),
    //   lane = idx 0..4 (qubits 11..7), warp = idx 5..7 (qubits 6,5,4).
    // Transposed T: SX[k]/SY[k] hold idx tb|(k<<5) (lo) and |0x10 (hi) with
    //   tb = (tid&0xF) | ((tid>>5)<<8) | (((tid>>4)&1)<<11).
    //   k bits = idx 5..7 (qubits 6,5,4), pack = idx 4 (qubit 7).
    u64 SX[8], SY[8];
    const int tb = (tid & 0xF) | ((tid >> 5) << 8) | (((tid >> 4) & 1) << 11);
    const int dt = permdst(tb);   // per-thread part of the linear perm

    // ---- init product state directly in T layout (layer-0 gates folded) ----
    {
        float2 cm = (tid & 1) ? v1s[11] : v0s[11];
        cm = cmulc(cm, (tid & 2) ? v1s[10] : v0s[10]);
        cm = cmulc(cm, (tid & 4) ? v1s[9] : v0s[9]);
        cm = cmulc(cm, (tid & 8) ? v1s[8] : v0s[8]);
        cm = cmulc(cm, ((tid >> 4) & 1) ? v1s[0] : v0s[0]);
        cm = cmulc(cm, ((tid >> 5) & 1) ? v1s[3] : v0s[3]);
        cm = cmulc(cm, ((tid >> 6) & 1) ? v1s[2] : v0s[2]);
        cm = cmulc(cm, ((tid >> 7) & 1) ? v1s[1] : v0s[1]);
        float2 q7a = v0s[7], q7b = v1s[7];
        #pragma unroll
        for (int k = 0; k < 8; k++) {
            float2 a = cm;
            a = cmulc(a, (k & 1) ? v1s[6] : v0s[6]);
            a = cmulc(a, (k & 2) ? v1s[5] : v0s[5]);
            a = cmulc(a, (k & 4) ? v1s[4] : v0s[4]);
            float2 lo = cmulc(a, q7a);
            float2 hi = cmulc(a, q7b);
            SX[k] = pk(lo.x, hi.x);
            SY[k] = pk(lo.y, hi.y);
        }
    }

    int b = 0;

    // ---- perm RT from T -> C (CNOT ring; CZ sign optional) ----
    // done as a lambda-ish macro body, repeated for layer 0 and layers 1..4
    #define RT_PERM(CZSEL)                                                     \
    {                                                                          \
        float2* fb = fsm + b * 4096;                                           \
        const unsigned czsel = (CZSEL);                                        \
        _Pragma("unroll")                                                      \
        for (int k = 0; k < 8; k++) {                                          \
            int d0 = dt ^ permdst(k << 5);                                     \
            int d1 = d0 ^ 0x81F;                                               \
            float xl, xh, yl, yh;                                              \
            upk(SX[k], xl, xh); upk(SY[k], yl, yh);                            \
            unsigned g0 = ((unsigned)__popc((d0 & (d0 >> 2)) & 0x2AA) & czsel) << 31; \
            unsigned g1 = ((unsigned)__popc((d1 & (d1 >> 2)) & 0x2AA) & czsel) << 31; \
            xl = __uint_as_float(__float_as_uint(xl) ^ g0);                    \
            yl = __uint_as_float(__float_as_uint(yl) ^ g0);                    \
            xh = __uint_as_float(__float_as_uint(xh) ^ g1);                    \
            yh = __uint_as_float(__float_as_uint(yh) ^ g1);                    \
            fb[d0] = make_float2(xl, yl);                                      \
            fb[d1] = make_float2(xh, yh);                                      \
        }                                                                      \
        __syncthreads();                                                       \
        _Pragma("unroll")                                                      \
        for (int k = 0; k < 8; k++) {                                          \
            int a0 = (k << 8) | tid;                                           \
            float2 lo = fb[a0], hi = fb[a0 | 0x800];                           \
            SX[k] = pk(lo.x, hi.x);                                            \
            SY[k] = pk(lo.y, hi.y);                                            \
        }                                                                      \
        b ^= 1;                                                                \
    }

    RT_PERM(0u)   // layer-0 CNOT ring (no CZ)

    // ---- layers 1..5 ----
    for (int l = 1; l < 6; l++) {
        const float4* M = Mm[l - 1];

        // C phase: k-gates qubits 3,2,1 ; pack gate qubit 0 ; sgates 11,10,9,8
        kgate(SX, SY, M[3], 0);
        kgate(SX, SY, M[2], 1);
        kgate(SX, SY, M[1], 2);
        pgate(SX, SY, M[0]);
        sgate(SX, SY, M[11], 0, lane);
        sgate(SX, SY, M[10], 1, lane);
        sgate(SX, SY, M[9], 2, lane);
        sgate(SX, SY, M[8], 3, lane);

        // transpose C -> T (warp bits + lane bit 4 become register/pack bits)
        {
            float2* fb = fsm + b * 4096;
            #pragma unroll
            for (int k = 0; k < 8; k++) {
                int i0 = (k << 8) | tid;
                float xl, xh, yl, yh;
                upk(SX[k], xl, xh); upk(SY[k], yl, yh);
                fb[i0] = make_float2(xl, yl);
                fb[i0 | 0x800] = make_float2(xh, yh);
            }
            __syncthreads();
            #pragma unroll
            for (int k = 0; k < 8; k++) {
                int a0 = tb | (k << 5);
                float2 lo = fb[a0], hi = fb[a0 | 0x10];
                SX[k] = pk(lo.x, hi.x);
                SY[k] = pk(lo.y, hi.y);
            }
            b ^= 1;
        }

        // T phase: k-gates qubits 6,5,4 ; pack gate qubit 7
        kgate(SX, SY, M[6], 0);
        kgate(SX, SY, M[5], 1);
        kgate(SX, SY, M[4], 2);
        pgate(SX, SY, M[7]);

        // perm RT back to C (CZ folded on odd layers); layer 5 folds into meas
        if (l < 5) RT_PERM((unsigned)(l & 1))
    }
    #undef RT_PERM

    // ---- measurement from T layout; layer-5 perm folded into signs ----
    // pack partner flips d11 (0x81F) but not d10/d9.
    float z0 = 0.f, z1 = 0.f, z2 = 0.f;
    #pragma unroll
    for (int k = 0; k < 8; k++) {
        int d0 = dt ^ permdst(k << 5);
        u64 P = f2(SY[k], SY[k], m2(SX[k], SX[k]));
        float pl, ph; upk(P, pl, ph);
        float sum = pl + ph, dif = pl - ph;
        z0 += ((d0 >> 11) & 1) ? -dif : dif;
        z1 += ((d0 >> 10) & 1) ? -sum : sum;
        z2 += ((d0 >> 9) & 1) ? -sum : sum;
    }
    #pragma unroll
    for (int o = 16; o; o >>= 1) {
        z0 += __shfl_xor_sync(~0u, z0, o);
        z1 += __shfl_xor_sync(~0u, z1, o);
        z2 += __shfl_xor_sync(~0u, z2, o);
    }
    if (lane == 0) { wz[wid][0] = z0; wz[wid][1] = z1; wz[wid][2] = z2; }
    __syncthreads();
    if (tid < 3) {
        float t = 0.f;
        #pragma unroll
        for (int w = 0; w < 8; w++) t += wz[w][tid];
        qv[tid] = t;
    }
    __syncthreads();

    // ---- head: gelu(q @ W4^T + b4) @ W5^T + b5 ----
    if (tid < 32) {
        float acc = b4[tid];
        acc = fmaf(W4[tid * 3 + 0], qv[0], acc);
        acc = fmaf(W4[tid * 3 + 1], qv[1], acc);
        acc = fmaf(W4[tid * 3 + 2], qv[2], acc);
        h4s[tid] = gelu_f(acc);
    }
    __syncthreads();
    if (tid < 64) {
        const float* wr = W5 + tid * 32;
        float acc = b5[tid];
        #pragma unroll
        for (int j = 0; j < 32; j++) acc = fmaf(wr[j], h4s[j], acc);
        out[bidx * 64 + tid] = acc;
    }
}

extern "C" void kernel_launch(void* const* d_in, const int* in_sizes, int n_in,
                              void* d_out, int out_size)
{
    const float* x    = (const float*)d_in[0];
    const float* W1   = (const float*)d_in[1];
    const float* b1   = (const float*)d_in[2];
    const float* g_ln = (const float*)d_in[3];
    const float* b_ln = (const float*)d_in[4];
    const float* W2   = (const float*)d_in[5];
    const float* b2   = (const float*)d_in[6];
    const float* W3   = (const float*)d_in[7];
    const float* b3   = (const float*)d_in[8];
    const float* qw   = (const float*)d_in[9];
    const float* W4   = (const float*)d_in[10];
    const float* b4   = (const float*)d_in[11];
    const float* W5   = (const float*)d_in[12];
    const float* b5   = (const float*)d_in[13];

    const size_t shmem = 8192 * sizeof(float2);  // 64 KB: 2 ping-pong buffers
    cudaFuncSetAttribute(qpu_kernel, cudaFuncAttributeMaxDynamicSharedMemorySize,
                         (int)shmem);
    qpu_kernel<<<NB, TPB, shmem>>>(x, W1, b1, g_ln, b_ln, W2, b2, W3, b3, qw,
                                   W4, b4, W5, b5, (float*)d_out);
}

// round 6
// speedup vs baseline: 1.1348x; 1.0049x over previous
#include <cuda_runtime.h>
#include <math.h>

#define NQ 12
#define TPB 256
#define NB 256

typedef unsigned long long u64;

__device__ __forceinline__ u64 pk(float lo, float hi) {
    u64 r;
    asm("mov.b64 %0,{%1,%2};" : "=l"(r)
        : "r"(__float_as_uint(lo)), "r"(__float_as_uint(hi)));
    return r;
}
__device__ __forceinline__ void upk(u64 v, float& lo, float& hi) {
    unsigned a, b;
    asm("mov.b64 {%0,%1},%2;" : "=r"(a), "=r"(b) : "l"(v));
    lo = __uint_as_float(a); hi = __uint_as_float(b);
}
__device__ __forceinline__ u64 sp(float f) { return pk(f, f); }
__device__ __forceinline__ u64 f2(u64 a, u64 b, u64 c) {
    u64 d;
    asm("fma.rn.f32x2 %0,%1,%2,%3;" : "=l"(d) : "l"(a), "l"(b), "l"(c));
    return d;
}
__device__ __forceinline__ u64 m2(u64 a, u64 b) {
    u64 d;
    asm("mul.rn.f32x2 %0,%1,%2;" : "=l"(d) : "l"(a), "l"(b));
    return d;
}
__device__ __forceinline__ u64 swp(u64 v) {
    float l, h; upk(v, l, h); return pk(h, l);
}

__device__ __forceinline__ float2 cmulc(float2 x, float2 y) {
    return make_float2(x.x * y.x - x.y * y.y, x.x * y.y + x.y * y.x);
}

__device__ __forceinline__ float gelu_f(float x) {
    return 0.5f * x * (1.0f + erff(x * 0.7071067811865476f));
}

// Composed CNOT-ring permutation (CNOT(0,1)..CNOT(10,11),CNOT(11,0)).
// Qubit w lives at bit position (11-w). LINEAR over GF(2).
__device__ __forceinline__ int permdst(int idx) {
    int y = idx;
    y ^= y >> 1; y ^= y >> 2; y ^= y >> 4; y ^= y >> 8;
    return (y & 0x7FF) | (((y ^ (idx >> 11)) & 1) << 11);
}

// ---- symmetric-form gates: float4 m = (U0.x,U0.y,U1.x,U1.y),
//      U11 = conj(U00), U10 = (-U01.x, U01.y). Survives the RY fold. ----

__device__ __forceinline__ void kgate(u64* SX, u64* SY, float4 m, int rb)
{
    u64 g0x = sp(m.x),  g0y = sp(m.y), g0yn = sp(-m.y);
    u64 g1x = sp(m.z),  g1xn = sp(-m.z);
    u64 g1y = sp(m.w),  g1yn = sp(-m.w);
    #pragma unroll
    for (int k = 0; k < 8; k++) {
        if (!((k >> rb) & 1)) {
            const int k1 = k | (1 << rb);
            u64 X0 = SX[k], Y0 = SY[k], X1 = SX[k1], Y1 = SY[k1];
            SX[k]  = f2(g1yn, Y1, f2(g1x, X1, f2(g0yn, Y0, m2(g0x, X0))));
            SY[k]  = f2(g1y,  X1, f2(g1x, Y1, f2(g0y,  X0, m2(g0x, Y0))));
            SX[k1] = f2(g0y,  Y1, f2(g0x, X1, f2(g1yn, Y0, m2(g1xn, X0))));
            SY[k1] = f2(g0yn, X1, f2(g0x, Y1, f2(g1y,  X0, m2(g1xn, Y0))));
        }
    }
}

__device__ __forceinline__ void pgate(u64* SX, u64* SY, float4 m)
{
    u64 Dx  = sp(m.x);
    u64 Dy  = pk(m.y, -m.y), Dyn = pk(-m.y, m.y);
    u64 Ox  = pk(m.z, -m.z);
    u64 Oy  = sp(m.w), Oyn = sp(-m.w);
    #pragma unroll
    for (int k = 0; k < 8; k++) {
        u64 sX = swp(SX[k]), sY = swp(SY[k]);
        u64 nX = f2(Oyn, sY, f2(Ox, sX, f2(Dyn, SY[k], m2(Dx, SX[k]))));
        u64 nY = f2(Oy,  sX, f2(Ox, sY, f2(Dy,  SX[k], m2(Dx, SY[k]))));
        SX[k] = nX; SY[k] = nY;
    }
}

__device__ __forceinline__ void sgate(u64* SX, u64* SY, float4 m, int p, int lane)
{
    const int sb = (lane >> p) & 1;
    float dY = sb ? -m.y : m.y;
    float oX = sb ? -m.z : m.z;
    u64 gdx = sp(m.x), gdy = sp(dY), gdyn = sp(-dY);
    u64 gox = sp(oX),  goy = sp(m.w), goyn = sp(-m.w);
    #pragma unroll
    for (int k = 0; k < 8; k++) {
        float xl, xh, yl, yh;
        upk(SX[k], xl, xh); upk(SY[k], yl, yh);
        float oxl = __shfl_xor_sync(~0u, xl, 1 << p);
        float oxh = __shfl_xor_sync(~0u, xh, 1 << p);
        float oyl = __shfl_xor_sync(~0u, yl, 1 << p);
        float oyh = __shfl_xor_sync(~0u, yh, 1 << p);
        u64 OX = pk(oxl, oxh), OY = pk(oyl, oyh);
        u64 nX = f2(goyn, OY, f2(gox, OX, f2(gdyn, SY[k], m2(gdx, SX[k]))));
        u64 nY = f2(goy,  OX, f2(gox, OY, f2(gdy,  SX[k], m2(gdx, SY[k]))));
        SX[k] = nX; SY[k] = nY;
    }
}

__global__ void __launch_bounds__(TPB, 2)
qpu_kernel(const float* __restrict__ x,
           const float* __restrict__ W1, const float* __restrict__ b1,
           const float* __restrict__ g_ln, const float* __restrict__ b_ln,
           const float* __restrict__ W2, const float* __restrict__ b2,
           const float* __restrict__ W3, const float* __restrict__ b3,
           const float* __restrict__ qw,
           const float* __restrict__ W4, const float* __restrict__ b4,
           const float* __restrict__ W5, const float* __restrict__ b5,
           float* __restrict__ out)
{
    // dynamic: 2 ping-pong float2 buffers, 4096 each = 64 KB
    extern __shared__ float2 fsm[];
    __shared__ __align__(16) float xrow[256];
    __shared__ __align__(16) float h1s[128];
    __shared__ __align__(16) float hns[128];
    __shared__ __align__(16) float h2s[64];
    __shared__ float4 Mm[5][NQ];          // merged gates (U0.x,U0.y,U1.x,U1.y)
    __shared__ float2 v0s[NQ], v1s[NQ];   // initial per-qubit product-state vectors
    __shared__ float cqs[NQ], sqs[NQ];    // re-upload RY half-angle cos/sin
    __shared__ float red0[8], red1[8];
    __shared__ float stats[2];
    __shared__ float wz[8][3];
    __shared__ float qv[3];
    __shared__ float h4s[32];

    const int tid = threadIdx.x;
    const int bidx = blockIdx.x;
    const int lane = tid & 31, wid = tid >> 5;

    xrow[tid] = x[bidx * 256 + tid];
    __syncthreads();

    // ---- h1 = gelu(x @ W1^T + b1), 128 outputs ----
    if (tid < 128) {
        const float4* wr = (const float4*)(W1 + tid * 256);
        const float4* xr = (const float4*)xrow;
        float acc0 = 0.f, acc1 = 0.f;
        #pragma unroll 8
        for (int k = 0; k < 64; k += 2) {
            float4 w = wr[k], xv = xr[k];
            acc0 = fmaf(w.x, xv.x, acc0); acc0 = fmaf(w.y, xv.y, acc0);
            acc0 = fmaf(w.z, xv.z, acc0); acc0 = fmaf(w.w, xv.w, acc0);
            float4 w2_ = wr[k + 1], xv2 = xr[k + 1];
            acc1 = fmaf(w2_.x, xv2.x, acc1); acc1 = fmaf(w2_.y, xv2.y, acc1);
            acc1 = fmaf(w2_.z, xv2.z, acc1); acc1 = fmaf(w2_.w, xv2.w, acc1);
        }
        h1s[tid] = gelu_f(acc0 + acc1 + b1[tid]);
    }
    __syncthreads();

    // ---- layernorm over 128 ----
    {
        float v = (tid < 128) ? h1s[tid] : 0.f;
        float s = v, ss = v * v;
        #pragma unroll
        for (int o = 16; o; o >>= 1) {
            s += __shfl_xor_sync(~0u, s, o);
            ss += __shfl_xor_sync(~0u, ss, o);
        }
        if (lane == 0) { red0[wid] = s; red1[wid] = ss; }
    }
    __syncthreads();
    if (tid == 0) {
        float s = 0.f, ss = 0.f;
        #pragma unroll
        for (int w = 0; w < 8; w++) { s += red0[w]; ss += red1[w]; }
        float mu = s * (1.f / 128.f);
        float var = ss * (1.f / 128.f) - mu * mu;
        stats[0] = mu; stats[1] = rsqrtf(var + 1e-5f);
    }
    __syncthreads();
    if (tid < 128)
        hns[tid] = (h1s[tid] - stats[0]) * stats[1] * g_ln[tid] + b_ln[tid];
    __syncthreads();

    // ---- h2 = gelu(hn @ W2^T + b2), 64 outputs ----
    if (tid < 64) {
        const float4* wr = (const float4*)(W2 + tid * 128);
        const float4* hr = (const float4*)hns;
        float acc = 0.f;
        #pragma unroll 8
        for (int k = 0; k < 32; k++) {
            float4 w = wr[k], h = hr[k];
            acc = fmaf(w.x, h.x, acc); acc = fmaf(w.y, h.y, acc);
            acc = fmaf(w.z, h.z, acc); acc = fmaf(w.w, h.w, acc);
        }
        h2s[tid] = gelu_f(acc + b2[tid]);
    }
    __syncthreads();

    // ---- xq = tanh(h2 @ W3^T + b3); enc = xq*pi^2; init vectors + re-upload cs ----
    if (tid < NQ) {
        const float* wr = W3 + tid * 64;
        float acc = 0.f;
        #pragma unroll
        for (int k = 0; k < 64; k++) acc = fmaf(wr[k], h2s[k], acc);
        float xqv = tanhf(acc + b3[tid]);
        float e = xqv * 9.869604401089358f;   // pi^2
        float se, ce; sincosf(0.5f * e, &se, &ce);
        const float* wp = qw + tid * 3;
        float w0 = wp[0], w1 = wp[1], w2v = wp[2];
        float sh, ch; sincosf(0.5f * w1, &sh, &ch);
        float sa, ca; sincosf(0.5f * (w0 + w2v), &sa, &ca);
        float sb, cb; sincosf(0.5f * (w0 - w2v), &sb, &cb);
        float2 u00 = make_float2(ch * ca, -ch * sa);
        float2 u01 = make_float2(-sh * cb, -sh * sb);
        float2 u10 = make_float2(sh * cb, -sh * sb);
        float2 u11 = make_float2(ch * ca, ch * sa);
        v0s[tid] = make_float2(u00.x * ce + u01.x * se, u00.y * ce + u01.y * se);
        v1s[tid] = make_float2(u10.x * ce + u11.x * se, u10.y * ce + u11.y * se);
        float s4, c4; sincosf(0.25f * e, &s4, &c4);
        cqs[tid] = c4; sqs[tid] = s4;
    }
    __syncthreads();

    // ---- merged gate matrices for layers 1..5 (symmetric form: U0,U1 only) ----
    if (tid < 60) {
        int L = tid / 12 + 1, q = tid - (L - 1) * 12;
        const float* wp = qw + (L * NQ + q) * 3;
        float w0 = wp[0], w1 = wp[1], w2v = wp[2];
        float sh, ch; sincosf(0.5f * w1, &sh, &ch);
        float sa, ca; sincosf(0.5f * (w0 + w2v), &sa, &ca);
        float sb, cb; sincosf(0.5f * (w0 - w2v), &sb, &cb);
        float2 U0 = make_float2(ch * ca, -ch * sa);
        float2 U1 = make_float2(-sh * cb, -sh * sb);
        if (L & 1) {   // fold RY(enc/2) re-upload (emitted after even layers)
            float cf = cqs[q], sf = sqs[q];
            float2 n0 = make_float2(U0.x * cf + U1.x * sf, U0.y * cf + U1.y * sf);
            float2 n1 = make_float2(-U0.x * sf + U1.x * cf, -U0.y * sf + U1.y * cf);
            U0 = n0; U1 = n1;
        }
        Mm[L - 1][q] = make_float4(U0.x, U0.y, U1.x, U1.y);
    }
    __syncthreads();

    // ============ statevector ============
    // Canonical C: SX[k]/SY[k] hold idx (k<<8)|tid (lo) and |0x800 (hi).
    // Transposed T: SX[k]/SY[k] hold idx tb|(k<<5) (lo) and |0x10 (hi), with
    //   tb = (tid&0xF) | ((tid>>5)<<8) | (((tid>>4)&1)<<11).
    u64 SX[8], SY[8];
    const int tb = (tid & 0xF) | ((tid >> 5) << 8) | (((tid >> 4) & 1) << 11);
    const int dt = permdst(tb);   // per-thread part of the linear perm

    // precomputed CZ sign masks: bit k = sign for dst of (lo / hi) element k
    unsigned czm0 = 0, czm1 = 0;
    #pragma unroll
    for (int k = 0; k < 8; k++) {
        int d0 = dt ^ permdst(k << 5);   // permdst(k<<5) folds to a constant
        int d1 = d0 ^ 0x81F;             // pack-partner dst (flip idx bit 4)
        czm0 |= ((unsigned)__popc((d0 & (d0 >> 2)) & 0x2AA) & 1u) << k;
        czm1 |= ((unsigned)__popc((d1 & (d1 >> 2)) & 0x2AA) & 1u) << k;
    }

    // ---- init product state directly in T layout (layer-0 gates folded) ----
    {
        float2 cm = (tid & 1) ? v1s[11] : v0s[11];
        cm = cmulc(cm, (tid & 2) ? v1s[10] : v0s[10]);
        cm = cmulc(cm, (tid & 4) ? v1s[9] : v0s[9]);
        cm = cmulc(cm, (tid & 8) ? v1s[8] : v0s[8]);
        cm = cmulc(cm, ((tid >> 4) & 1) ? v1s[0] : v0s[0]);
        cm = cmulc(cm, ((tid >> 5) & 1) ? v1s[3] : v0s[3]);
        cm = cmulc(cm, ((tid >> 6) & 1) ? v1s[2] : v0s[2]);
        cm = cmulc(cm, ((tid >> 7) & 1) ? v1s[1] : v0s[1]);
        float2 q7a = v0s[7], q7b = v1s[7];
        #pragma unroll
        for (int k = 0; k < 8; k++) {
            float2 a = cm;
            a = cmulc(a, (k & 1) ? v1s[6] : v0s[6]);
            a = cmulc(a, (k & 2) ? v1s[5] : v0s[5]);
            a = cmulc(a, (k & 4) ? v1s[4] : v0s[4]);
            float2 lo = cmulc(a, q7a);
            float2 hi = cmulc(a, q7b);
            SX[k] = pk(lo.x, hi.x);
            SY[k] = pk(lo.y, hi.y);
        }
    }

    int b = 0;

    // ---- perm RT from T -> C. Scatter applies CNOT ring (+optional CZ of this
    //      layer); gather applies the NEXT layer's qubit-11 gate (idx bit 0)
    //      via partner reads (gate-on-read replaces one shuffle-gate). ----
    #define RT_PERM(CZSEL, MN)                                                 \
    {                                                                          \
        float2* fb = fsm + b * 4096;                                           \
        const unsigned czsel = (CZSEL);                                        \
        _Pragma("unroll")                                                      \
        for (int k = 0; k < 8; k++) {                                          \
            int d0 = dt ^ permdst(k << 5);                                     \
            float xl, xh, yl, yh;                                              \
            upk(SX[k], xl, xh); upk(SY[k], yl, yh);                            \
            unsigned g0 = ((czm0 >> k) & czsel) << 31;                         \
            unsigned g1 = ((czm1 >> k) & czsel) << 31;                         \
            xl = __uint_as_float(__float_as_uint(xl) ^ g0);                    \
            yl = __uint_as_float(__float_as_uint(yl) ^ g0);                    \
            xh = __uint_as_float(__float_as_uint(xh) ^ g1);                    \
            yh = __uint_as_float(__float_as_uint(yh) ^ g1);                    \
            fb[d0] = make_float2(xl, yl);                                      \
            fb[d0 ^ 0x81F] = make_float2(xh, yh);                              \
        }                                                                      \
        __syncthreads();                                                       \
        {                                                                      \
            const float4 mg = (MN);                                            \
            const int sbq = tid & 1;                                           \
            float dyv = sbq ? -mg.y : mg.y;                                    \
            float oxv = sbq ? -mg.z : mg.z;                                    \
            u64 gdx = sp(mg.x), gdy = sp(dyv), gdyn = sp(-dyv);                \
            u64 gox = sp(oxv), goy = sp(mg.w), goyn = sp(-mg.w);               \
            _Pragma("unroll")                                                  \
            for (int k = 0; k < 8; k++) {                                      \
                int a0 = (k << 8) | tid;                                       \
                float2 ol = fb[a0], oh = fb[a0 | 0x800];                       \
                float2 pl = fb[a0 ^ 1], ph = fb[(a0 | 0x800) ^ 1];             \
                u64 Xo = pk(ol.x, oh.x), Yo = pk(ol.y, oh.y);                  \
                u64 Xp = pk(pl.x, ph.x), Yp = pk(pl.y, ph.y);                  \
                SX[k] = f2(goyn, Yp, f2(gox, Xp, f2(gdyn, Yo, m2(gdx, Xo))));  \
                SY[k] = f2(goy,  Xp, f2(gox, Yp, f2(gdy,  Xo, m2(gdx, Yo))));  \
            }                                                                  \
        }                                                                      \
        b ^= 1;                                                                \
    }

    // layer-0 CNOT ring (no CZ); gather applies layer-1 qubit-11 gate
    RT_PERM(0u, Mm[0][11])

    // ---- layers 1..5 ----
    for (int l = 1; l < 6; l++) {
        const float4* M = Mm[l - 1];

        // C phase: qubit 11 already applied at previous RT gather.
        // kgates qubits 3,2,1 ; pack gate qubit 0 ; sgates qubits 10,9.
        kgate(SX, SY, M[3], 0);
        kgate(SX, SY, M[2], 1);
        kgate(SX, SY, M[1], 2);
        pgate(SX, SY, M[0]);
        sgate(SX, SY, M[10], 1, lane);
        sgate(SX, SY, M[9], 2, lane);

        // transpose C -> T; gather applies qubit-8 gate (idx bit 3) on read
        {
            float2* fb = fsm + b * 4096;
            #pragma unroll
            for (int k = 0; k < 8; k++) {
                int i0 = (k << 8) | tid;
                float xl, xh, yl, yh;
                upk(SX[k], xl, xh); upk(SY[k], yl, yh);
                fb[i0] = make_float2(xl, yl);
                fb[i0 | 0x800] = make_float2(xh, yh);
            }
            __syncthreads();
            const float4 mg = M[8];
            const int sbq = (tid >> 3) & 1;
            float dyv = sbq ? -mg.y : mg.y;
            float oxv = sbq ? -mg.z : mg.z;
            u64 gdx = sp(mg.x), gdy = sp(dyv), gdyn = sp(-dyv);
            u64 gox = sp(oxv), goy = sp(mg.w), goyn = sp(-mg.w);
            #pragma unroll
            for (int k = 0; k < 8; k++) {
                int a0 = tb | (k << 5);
                float2 ol = fb[a0], oh = fb[a0 | 0x10];
                float2 pl = fb[a0 ^ 8], ph = fb[(a0 | 0x10) ^ 8];
                u64 Xo = pk(ol.x, oh.x), Yo = pk(ol.y, oh.y);
                u64 Xp = pk(pl.x, ph.x), Yp = pk(pl.y, ph.y);
                SX[k] = f2(goyn, Yp, f2(gox, Xp, f2(gdyn, Yo, m2(gdx, Xo))));
                SY[k] = f2(goy,  Xp, f2(gox, Yp, f2(gdy,  Xo, m2(gdx, Yo))));
            }
            b ^= 1;
        }

        // T phase: kgates qubits 6,5,4 ; pack gate qubit 7
        kgate(SX, SY, M[6], 0);
        kgate(SX, SY, M[5], 1);
        kgate(SX, SY, M[4], 2);
        pgate(SX, SY, M[7]);

        // perm RT back to C (CZ folded on odd layers); gather applies next
        // layer's qubit-11 gate. Layer 5's perm folds into measurement.
        if (l < 5) RT_PERM((unsigned)(l & 1), Mm[l][11])
    }
    #undef RT_PERM

    // ---- measurement from T layout; layer-5 perm folded into signs ----
    float z0 = 0.f, z1 = 0.f, z2 = 0.f;
    #pragma unroll
    for (int k = 0; k < 8; k++) {
        int d0 = dt ^ permdst(k << 5);
        u64 P = f2(SY[k], SY[k], m2(SX[k], SX[k]));
        float pl, ph; upk(P, pl, ph);
        float sum = pl + ph, dif = pl - ph;
        z0 += ((d0 >> 11) & 1) ? -dif : dif;
        z1 += ((d0 >> 10) & 1) ? -sum : sum;
        z2 += ((d0 >> 9) & 1) ? -sum : sum;
    }
    #pragma unroll
    for (int o = 16; o; o >>= 1) {
        z0 += __shfl_xor_sync(~0u, z0, o);
        z1 += __shfl_xor_sync(~0u, z1, o);
        z2 += __shfl_xor_sync(~0u, z2, o);
    }
    if (lane == 0) { wz[wid][0] = z0; wz[wid][1] = z1; wz[wid][2] = z2; }
    __syncthreads();
    if (tid < 3) {
        float t = 0.f;
        #pragma unroll
        for (int w = 0; w < 8; w++) t += wz[w][tid];
        qv[tid] = t;
    }
    __syncthreads();

    // ---- head: gelu(q @ W4^T + b4) @ W5^T + b5 ----
    if (tid < 32) {
        float acc = b4[tid];
        acc = fmaf(W4[tid * 3 + 0], qv[0], acc);
        acc = fmaf(W4[tid * 3 + 1], qv[1], acc);
        acc = fmaf(W4[tid * 3 + 2], qv[2], acc);
        h4s[tid] = gelu_f(acc);
    }
    __syncthreads();
    if (tid < 64) {
        const float* wr = W5 + tid * 32;
        float acc = b5[tid];
        #pragma unroll
        for (int j = 0; j < 32; j++) acc = fmaf(wr[j], h4s[j], acc);
        out[bidx * 64 + tid] = acc;
    }
}

extern "C" void kernel_launch(void* const* d_in, const int* in_sizes, int n_in,
                              void* d_out, int out_size)
{
    const float* x    = (const float*)d_in[0];
    const float* W1   = (const float*)d_in[1];
    const float* b1   = (const float*)d_in[2];
    const float* g_ln = (const float*)d_in[3];
    const float* b_ln = (const float*)d_in[4];
    const float* W2   = (const float*)d_in[5];
    const float* b2   = (const float*)d_in[6];
    const float* W3   = (const float*)d_in[7];
    const float* b3   = (const float*)d_in[8];
    const float* qw   = (const float*)d_in[9];
    const float* W4   = (const float*)d_in[10];
    const float* b4   = (const float*)d_in[11];
    const float* W5   = (const float*)d_in[12];
    const float* b5   = (const float*)d_in[13];

    const size_t shmem = 8192 * sizeof(float2);  // 64 KB: 2 ping-pong buffers
    cudaFuncSetAttribute(qpu_kernel, cudaFuncAttributeMaxDynamicSharedMemorySize,
                         (int)shmem);
    qpu_kernel<<<NB, TPB, shmem>>>(x, W1, b1, g_ln, b_ln, W2, b2, W3, b3, qw,
                                   W4, b4, W5, b5, (float*)d_out);
}